// round 10
// baseline (speedup 1.0000x reference)
#include <cuda_runtime.h>
#include <cfloat>

#define B_    16
#define F_    256
#define C_    64
#define HW_   4096
#define NE_   512
#define ZTOT_ (B_*C_*HW_)    /* 4194304 */
#define NTOK_ (ZTOT_/64)     /* 65536 */
#define NBLK_VQ (NTOK_/64)   /* 1024 */
#define FULLMASK 0xffffffffu

// ---------------- scratch (device globals; no allocation) ----------------
__device__ __align__(16) float g_z[ZTOT_];        // conv2 output (16 MiB)
__device__ float g_scale[F_], g_shift[F_];        // folded BN affine
__device__ __align__(16) float g_Wt[F_*C_];       // fused weight, [f][o]
__device__ float g_beff[C_];
__device__ float g_en[NE_], g_e2[NE_];
__device__ float g_var[NE_], g_cm2[NE_];
__device__ float g_mse_part[NBLK_VQ];
__device__ float g_hsw;

// ---------------- K1: BatchNorm statistics (per feature channel) ----------
__global__ __launch_bounds__(256) void k_bn(const float* __restrict__ x,
                                            const float* __restrict__ gamma,
                                            const float* __restrict__ beta)
{
    int f = blockIdx.x, tid = threadIdx.x;
    float s = 0.f, ss = 0.f;
    const float* xf = x + (size_t)f * HW_;
    for (int b = 0; b < B_; b++) {
        const float* p = xf + (size_t)b * F_ * HW_;
        for (int i = tid; i < HW_; i += 256) { float v = p[i]; s += v; ss += v * v; }
    }
    __shared__ float sh[256], sh2[256];
    sh[tid] = s; sh2[tid] = ss; __syncthreads();
    for (int o = 128; o > 0; o >>= 1) {
        if (tid < o) { sh[tid] += sh[tid + o]; sh2[tid] += sh2[tid + o]; }
        __syncthreads();
    }
    if (tid == 0) {
        const float n = (float)(B_ * HW_);
        float mu  = sh[0] / n;
        float var = sh2[0] / n - mu * mu;
        float sc  = gamma[f] * (1.0f / sqrtf(var + 1e-5f));
        g_scale[f] = sc;
        g_shift[f] = beta[f] - mu * sc;
    }
}

// ---------------- K2: fuse conv2∘conv1∘BN into one weight ----------------
__global__ __launch_bounds__(256) void k_fuse(const float* __restrict__ w1,
                                              const float* __restrict__ b1,
                                              const float* __restrict__ w2,
                                              const float* __restrict__ b2)
{
    int o = blockIdx.x, f = threadIdx.x;
    float d = 0.f;
#pragma unroll 8
    for (int c = 0; c < C_; c++) d += w2[o * C_ + c] * w1[c * F_ + f];
    g_Wt[f * C_ + o] = d * g_scale[f];           // transposed [f][o] for coalesced tiles
    __shared__ float sh[256];
    sh[f] = d * g_shift[f];
    __syncthreads();
    for (int s = 128; s > 0; s >>= 1) { if (f < s) sh[f] += sh[f + s]; __syncthreads(); }
    if (f == 0) {
        float bv = b2[o];
        for (int c = 0; c < C_; c++) bv += w2[o * C_ + c] * b1[c];
        g_beff[o] = sh[0] + bv;
    }
}

// ---------------- K3: fused conv GEMM  z[b,o,p] = W_eff @ x ---------------
// BM=64(o) BN=128(p) BK=16, thread tile 8x4, 256 threads, grid (32, B)
// Two-level accumulation (per-tile partial then add) halves rounding error.
__global__ __launch_bounds__(256) void k_conv(const float* __restrict__ x)
{
    __shared__ float Ws[16][64];
    __shared__ float Xs[16][128];
    int tid = threadIdx.x;
    int b   = blockIdx.y;
    int pb  = blockIdx.x * 128;
    const float* xb = x + (size_t)b * F_ * HW_ + pb;

    int ro = (tid >> 5) * 8;        // 8 output channels per thread (warp-uniform)
    int cp = (tid & 31) * 4;        // 4 pixels per thread

    float acc[8][4];
#pragma unroll
    for (int i = 0; i < 8; i++)
#pragma unroll
        for (int j = 0; j < 4; j++) acc[i][j] = 0.f;

    for (int kc = 0; kc < F_; kc += 16) {
        {
            int r = tid >> 4, c = (tid & 15) * 4;
            *(float4*)&Ws[r][c] = *(const float4*)&g_Wt[(kc + r) * C_ + c];
            int i0 = tid,        r0 = i0 >> 5, c0 = (i0 & 31) * 4;
            *(float4*)&Xs[r0][c0] = *(const float4*)&xb[(size_t)(kc + r0) * HW_ + c0];
            int i1 = tid + 256,  r1 = i1 >> 5, c1 = (i1 & 31) * 4;
            *(float4*)&Xs[r1][c1] = *(const float4*)&xb[(size_t)(kc + r1) * HW_ + c1];
        }
        __syncthreads();
        float tacc[8][4];
#pragma unroll
        for (int i = 0; i < 8; i++)
#pragma unroll
            for (int j = 0; j < 4; j++) tacc[i][j] = 0.f;
#pragma unroll
        for (int k = 0; k < 16; k++) {
            float4 bx = *(const float4*)&Xs[k][cp];
            float bv[4] = { bx.x, bx.y, bx.z, bx.w };
#pragma unroll
            for (int i = 0; i < 8; i++) {
                float a = Ws[k][ro + i];   // warp-uniform broadcast
#pragma unroll
                for (int j = 0; j < 4; j++) tacc[i][j] += a * bv[j];
            }
        }
#pragma unroll
        for (int i = 0; i < 8; i++)
#pragma unroll
            for (int j = 0; j < 4; j++) acc[i][j] += tacc[i][j];
        __syncthreads();
    }
    float* zrow = g_z + (size_t)b * C_ * HW_ + pb;
#pragma unroll
    for (int i = 0; i < 8; i++) {
        float be = g_beff[ro + i];
        float4 v;
        v.x = acc[i][0] + be; v.y = acc[i][1] + be;
        v.z = acc[i][2] + be; v.w = acc[i][3] + be;
        *(float4*)&zrow[(size_t)(ro + i) * HW_ + cp] = v;
    }
}

// ---------------- K4: codebook norms + hsw --------------------------------
__global__ void k_en(const float* __restrict__ emb, const float* __restrict__ r)
{
    int j = threadIdx.x;                 // 512 threads
    const float* e = emb + j * 64;
    float p0 = 0, p1 = 0, p2 = 0, p3 = 0;
#pragma unroll
    for (int k = 0; k < 64; k += 4) {
        p0 += e[k] * e[k];         p1 += e[k + 1] * e[k + 1];
        p2 += e[k + 2] * e[k + 2]; p3 += e[k + 3] * e[k + 3];
    }
    float s = (p0 + p1) + (p2 + p3);
    float en = sqrtf(s);
    g_e2[j] = s; g_en[j] = en;
    float d = r[j] - en;
    __shared__ float sh[512];
    sh[j] = d * d; __syncthreads();
    for (int o = 256; o > 0; o >>= 1) { if (j < o) sh[j] += sh[j + o]; __syncthreads(); }
    if (j == 0) g_hsw = sh[0] / 512.0f;
}

// ---------------- K5: angular stats (one row/column per block) ------------
__global__ __launch_bounds__(256) void k_cbstats(const float* __restrict__ emb)
{
    int j = blockIdx.x, tid = threadIdx.x;
    __shared__ float ej[64];
    __shared__ float ang[512];
    if (tid < 64) ej[tid] = emb[j * 64 + tid];
    __syncthreads();
    float enj = g_en[j];
    for (int i = tid; i < 512; i += 256) {
        const float* ei = emb + i * 64;
        float p0 = 0, p1 = 0, p2 = 0, p3 = 0;
#pragma unroll
        for (int k = 0; k < 64; k += 4) {
            p0 += ei[k] * ej[k];         p1 += ei[k + 1] * ej[k + 1];
            p2 += ei[k + 2] * ej[k + 2]; p3 += ei[k + 3] * ej[k + 3];
        }
        float d = (p0 + p1) + (p2 + p3);
        float c = d / (g_en[i] * enj);
        c = fminf(fmaxf(c, -0.99999f), 0.99999f);
        ang[i] = acosf(c);
    }
    __syncthreads();
    __shared__ float rs[256];
    float a0 = ang[tid], a1 = ang[tid + 256];
    rs[tid] = a0 + a1; __syncthreads();
    for (int o = 128; o > 0; o >>= 1) { if (tid < o) rs[tid] += rs[tid + o]; __syncthreads(); }
    float mean = rs[0] / 512.0f;
    __syncthreads();
    float d0 = a0 - mean, d1 = a1 - mean;
    rs[tid] = d0 * d0 + d1 * d1; __syncthreads();
    for (int o = 128; o > 0; o >>= 1) { if (tid < o) rs[tid] += rs[tid + o]; __syncthreads(); }
    if (tid == 0) g_var[j] = rs[0] / 511.0f;     // ddof=1
    // two smallest angles of this column (== sort(ang,axis=0)[1])
    __shared__ float m1s[256], m2s[256];
    m1s[tid] = fminf(a0, a1); m2s[tid] = fmaxf(a0, a1);
    __syncthreads();
    for (int o = 128; o > 0; o >>= 1) {
        if (tid < o) {
            float x1 = m1s[tid], x2 = m2s[tid];
            float y1 = m1s[tid + o], y2 = m2s[tid + o];
            float n1 = fminf(x1, y1);
            float n2 = fminf(fmaxf(x1, y1), fminf(x2, y2));
            m1s[tid] = n1; m2s[tid] = n2;
        }
        __syncthreads();
    }
    if (tid == 0) g_cm2[j] = m2s[0];
}

// ---------------- K6: VQ — distance GEMM + top-2 argmin + double re-rank ---
// block: 64 tokens x 512 codes; thread tile 8 tokens x 2 codes per 64-chunk
__global__ __launch_bounds__(256) void k_vq(const float* __restrict__ emb,
                                            float* __restrict__ zq)
{
    __shared__ float Zs[64][65];     // [k][token]  (stride 65 -> conflict-free cols)
    __shared__ float Es[64][66];     // [k][code]   chunk of 64 codes
    __shared__ float zsq_s[64];
    __shared__ float e2s[64];
    __shared__ float warp_mse[8];

    int tid = threadIdx.x;
    int t0  = blockIdx.x * 64;
    const float* zb = g_z + (size_t)t0 * 64;

#pragma unroll
    for (int it = 0; it < 16; it++) {
        int idx = tid + it * 256;              // 4096 elems
        Zs[idx & 63][idx >> 6] = zb[idx];      // coalesced read, transposed store
    }
    __syncthreads();
    if (tid < 64) {
        float p0 = 0, p1 = 0, p2 = 0, p3 = 0;
#pragma unroll
        for (int k = 0; k < 64; k += 4) {
            float a = Zs[k][tid], b = Zs[k + 1][tid], c = Zs[k + 2][tid], d = Zs[k + 3][tid];
            p0 += a * a; p1 += b * b; p2 += c * c; p3 += d * d;
        }
        zsq_s[tid] = (p0 + p1) + (p2 + p3);
    }

    int warp = tid >> 5, lane = tid & 31;
    int ro = warp * 8;          // 8 tokens per warp (warp-uniform)
    int ce = lane * 2;          // 2 codes per lane per chunk
    float v1[8], v2[8]; int i1[8], i2[8];
#pragma unroll
    for (int i = 0; i < 8; i++) { v1[i] = FLT_MAX; v2[i] = FLT_MAX; i1[i] = 0; i2[i] = 0; }

    for (int e0 = 0; e0 < NE_; e0 += 64) {
        __syncthreads();
#pragma unroll
        for (int it = 0; it < 16; it++) {
            int idx = tid + it * 256;
            int e = idx >> 6, k = idx & 63;
            Es[k][e] = emb[(e0 + e) * 64 + k];
        }
        if (tid < 64) e2s[tid] = g_e2[e0 + tid];
        __syncthreads();

        float acc[8][2];
#pragma unroll
        for (int i = 0; i < 8; i++) { acc[i][0] = 0.f; acc[i][1] = 0.f; }
#pragma unroll 4
        for (int k = 0; k < 64; k++) {
            float b0 = Es[k][ce], b1 = Es[k][ce + 1];
#pragma unroll
            for (int i = 0; i < 8; i++) {
                float a = Zs[k][ro + i];       // warp-uniform broadcast
                acc[i][0] += a * b0;
                acc[i][1] += a * b1;
            }
        }
#pragma unroll
        for (int i = 0; i < 8; i++) {
            float zq2 = zsq_s[ro + i];
#pragma unroll
            for (int j = 0; j < 2; j++) {
                float d = (zq2 + e2s[ce + j]) - 2.0f * acc[i][j];  // ref formula/order
                int ei = e0 + ce + j;
                if (d < v1[i])      { v2[i] = v1[i]; i2[i] = i1[i]; v1[i] = d; i1[i] = ei; }
                else if (d < v2[i]) { v2[i] = d; i2[i] = ei; }
            }
        }
    }

    float msum = 0.f;
#pragma unroll
    for (int i = 0; i < 8; i++) {
        float a1 = v1[i], a2 = v2[i]; int ai1 = i1[i], ai2 = i2[i];
        // warp tree-reduce top-2 with argmin-first tie-breaking
#pragma unroll
        for (int off = 16; off > 0; off >>= 1) {
            float b1 = __shfl_down_sync(FULLMASK, a1, off);
            int  bi1 = __shfl_down_sync(FULLMASK, ai1, off);
            float b2 = __shfl_down_sync(FULLMASK, a2, off);
            int  bi2 = __shfl_down_sync(FULLMASK, ai2, off);
            if (b1 < a1 || (b1 == a1 && bi1 < ai1)) {
                float s2; int si2;
                if (a1 < b2 || (a1 == b2 && ai1 < bi2)) { s2 = a1; si2 = ai1; }
                else                                     { s2 = b2; si2 = bi2; }
                a1 = b1; ai1 = bi1; a2 = s2; ai2 = si2;
            } else if (b1 < a2 || (b1 == a2 && bi1 < ai2)) {
                a2 = b1; ai2 = bi1;
            }
        }
        a1  = __shfl_sync(FULLMASK, a1, 0);  ai1 = __shfl_sync(FULLMASK, ai1, 0);
        a2  = __shfl_sync(FULLMASK, a2, 0);  ai2 = __shfl_sync(FULLMASK, ai2, 0);

        int tok = ro + i;
        int chosen = ai1;
        if (a2 - a1 < 2e-3f && ai2 != ai1) {
            // near-tie: exact double-precision re-rank of the two candidates
            const float* ea = emb + (size_t)ai1 * 64;
            const float* eb = emb + (size_t)ai2 * 64;
            double da = 0.0, db = 0.0;
#pragma unroll
            for (int h = 0; h < 2; h++) {
                int k = lane + h * 32;
                double zv = (double)Zs[k][tok];
                double u = zv - (double)ea[k]; da += u * u;
                double w = zv - (double)eb[k]; db += w * w;
            }
#pragma unroll
            for (int off = 16; off > 0; off >>= 1) {
                da += __shfl_down_sync(FULLMASK, da, off);
                db += __shfl_down_sync(FULLMASK, db, off);
            }
            da = __shfl_sync(FULLMASK, da, 0);
            db = __shfl_sync(FULLMASK, db, 0);
            if (db < da || (db == da && ai2 < ai1)) chosen = ai2;
        }

        const float* er = emb + (size_t)chosen * 64;
        float* orow = zq + (size_t)(t0 + tok) * 64;
#pragma unroll
        for (int h = 0; h < 2; h++) {
            int k = lane + h * 32;
            float zv = Zs[k][tok];
            float dv = er[k] - zv;
            orow[k] = zv + dv;              // z + sg(z_q - z), same rounding as ref
            msum += dv * dv;
        }
    }
#pragma unroll
    for (int off = 16; off > 0; off >>= 1)
        msum += __shfl_down_sync(FULLMASK, msum, off);
    if (lane == 0) warp_mse[warp] = msum;
    __syncthreads();
    if (tid == 0) {
        float s = 0.f;
#pragma unroll
        for (int w = 0; w < 8; w++) s += warp_mse[w];
        g_mse_part[blockIdx.x] = s;          // deterministic (no atomics)
    }
}

// ---------------- K7: finalize scalars -------------------------------------
__global__ void k_final(const float* __restrict__ r, float* __restrict__ out)
{
    int t = threadIdx.x;                 // 512 threads
    __shared__ float sh[512];

    sh[t] = g_mse_part[t] + g_mse_part[t + 512]; __syncthreads();
    for (int o = 256; o > 0; o >>= 1) { if (t < o) sh[t] += sh[t + o]; __syncthreads(); }
    float mse_sum = sh[0]; __syncthreads();

    sh[t] = g_var[t]; __syncthreads();
    for (int o = 256; o > 0; o >>= 1) { if (t < o) sh[t] += sh[t + o]; __syncthreads(); }
    float var_sum = sh[0]; __syncthreads();

    sh[t] = g_cm2[t]; __syncthreads();
    for (int o = 256; o > 0; o >>= 1) { if (t < o) sh[t] += sh[t + o]; __syncthreads(); }
    float cm2_sum = sh[0]; __syncthreads();

    sh[t] = fminf(fmaxf(r[t], 0.9f), 1.1f); __syncthreads();
    for (int o = 256; o > 0; o >>= 1) { if (t < o) sh[t] += sh[t + o]; __syncthreads(); }

    if (t == 0) {
        float mse = mse_sum * (1.0f / (float)ZTOT_);
        float cbv = var_sum * (1.0f / 512.0f);
        float tmd = cm2_sum * (1.0f / 512.0f);
        float hsw = g_hsw;
        float loss = ((mse + mse) + hsw) + (cbv - tmd);   // BETA = 1
        out[0] = loss;
        out[1 + ZTOT_ + 0] = cbv;
        out[1 + ZTOT_ + 1] = tmd;
        out[1 + ZTOT_ + 2] = hsw;
        out[1 + ZTOT_ + 3] = 0.0f;                        // cb_loss
        out[1 + ZTOT_ + 4] = sh[0] * (1.0f / 512.0f);     // mean_r
    }
}

// ---------------- launch ----------------------------------------------------
extern "C" void kernel_launch(void* const* d_in, const int* in_sizes, int n_in,
                              void* d_out, int out_size)
{
    (void)in_sizes; (void)n_in; (void)out_size;
    const float* x    = (const float*)d_in[0];
    const float* bng  = (const float*)d_in[1];
    const float* bnb  = (const float*)d_in[2];
    const float* w1   = (const float*)d_in[3];
    const float* b1   = (const float*)d_in[4];
    const float* w2   = (const float*)d_in[5];
    const float* b2   = (const float*)d_in[6];
    const float* emb  = (const float*)d_in[7];
    const float* r    = (const float*)d_in[8];
    float* out = (float*)d_out;

    k_bn     <<<F_,  256>>>(x, bng, bnb);
    k_fuse   <<<C_,  256>>>(w1, b1, w2, b2);
    k_conv   <<<dim3(HW_ / 128, B_), 256>>>(x);
    k_en     <<<1,   512>>>(emb, r);
    k_cbstats<<<NE_, 256>>>(emb);
    k_vq     <<<NBLK_VQ, 256>>>(emb, out + 1);
    k_final  <<<1,   512>>>(r, out);
}

// round 11
// speedup vs baseline: 1.0040x; 1.0040x over previous
#include <cuda_runtime.h>
#include <cfloat>

#define B_    16
#define F_    256
#define C_    64
#define HW_   4096
#define NE_   512
#define ZTOT_ (B_*C_*HW_)    /* 4194304 */
#define NTOK_ (ZTOT_/64)     /* 65536 */
#define NBLK_VQ (NTOK_/64)   /* 1024 */
#define FULLMASK 0xffffffffu

// ---------------- scratch (device globals; no allocation) ----------------
__device__ __align__(16) float g_z[ZTOT_];        // conv2 output (16 MiB)
__device__ float g_scale[F_], g_shift[F_];        // folded BN affine
__device__ __align__(16) float g_Wt[F_*C_];       // fused weight, [f][o]
__device__ float g_beff[C_];
__device__ float g_en[NE_], g_e2[NE_];
__device__ float g_var[NE_], g_cm2[NE_];
__device__ float g_mse_part[NBLK_VQ];
__device__ float g_hsw;

// ---------------- K1: BatchNorm statistics (per feature channel) ----------
__global__ __launch_bounds__(256) void k_bn(const float* __restrict__ x,
                                            const float* __restrict__ gamma,
                                            const float* __restrict__ beta)
{
    int f = blockIdx.x, tid = threadIdx.x;
    float s = 0.f, ss = 0.f;
    const float* xf = x + (size_t)f * HW_;
    for (int b = 0; b < B_; b++) {
        const float* p = xf + (size_t)b * F_ * HW_;
        for (int i = tid; i < HW_; i += 256) { float v = p[i]; s += v; ss += v * v; }
    }
    __shared__ float sh[256], sh2[256];
    sh[tid] = s; sh2[tid] = ss; __syncthreads();
    for (int o = 128; o > 0; o >>= 1) {
        if (tid < o) { sh[tid] += sh[tid + o]; sh2[tid] += sh2[tid + o]; }
        __syncthreads();
    }
    if (tid == 0) {
        const float n = (float)(B_ * HW_);
        float mu  = sh[0] / n;
        float var = sh2[0] / n - mu * mu;
        float sc  = gamma[f] * (1.0f / sqrtf(var + 1e-5f));
        g_scale[f] = sc;
        g_shift[f] = beta[f] - mu * sc;
    }
}

// ---------------- K2: fuse conv2∘conv1∘BN into one weight ----------------
__global__ __launch_bounds__(256) void k_fuse(const float* __restrict__ w1,
                                              const float* __restrict__ b1,
                                              const float* __restrict__ w2,
                                              const float* __restrict__ b2)
{
    int o = blockIdx.x, f = threadIdx.x;
    float d = 0.f;
#pragma unroll 8
    for (int c = 0; c < C_; c++) d += w2[o * C_ + c] * w1[c * F_ + f];
    g_Wt[f * C_ + o] = d * g_scale[f];           // transposed [f][o] for coalesced tiles
    __shared__ float sh[256];
    sh[f] = d * g_shift[f];
    __syncthreads();
    for (int s = 128; s > 0; s >>= 1) { if (f < s) sh[f] += sh[f + s]; __syncthreads(); }
    if (f == 0) {
        float bv = b2[o];
        for (int c = 0; c < C_; c++) bv += w2[o * C_ + c] * b1[c];
        g_beff[o] = sh[0] + bv;
    }
}

// ---------------- K3: fused conv GEMM  z[b,o,p] = W_eff @ x ---------------
// BM=64(o) BN=128(p) BK=16, thread tile 8x4, 256 threads, grid (32, B)
// Two-level accumulation (per-tile partial then add) halves rounding error.
__global__ __launch_bounds__(256) void k_conv(const float* __restrict__ x)
{
    __shared__ float Ws[16][64];
    __shared__ float Xs[16][128];
    int tid = threadIdx.x;
    int b   = blockIdx.y;
    int pb  = blockIdx.x * 128;
    const float* xb = x + (size_t)b * F_ * HW_ + pb;

    int ro = (tid >> 5) * 8;        // 8 output channels per thread (warp-uniform)
    int cp = (tid & 31) * 4;        // 4 pixels per thread

    float acc[8][4];
#pragma unroll
    for (int i = 0; i < 8; i++)
#pragma unroll
        for (int j = 0; j < 4; j++) acc[i][j] = 0.f;

    for (int kc = 0; kc < F_; kc += 16) {
        {
            int r = tid >> 4, c = (tid & 15) * 4;
            *(float4*)&Ws[r][c] = *(const float4*)&g_Wt[(kc + r) * C_ + c];
            int i0 = tid,        r0 = i0 >> 5, c0 = (i0 & 31) * 4;
            *(float4*)&Xs[r0][c0] = *(const float4*)&xb[(size_t)(kc + r0) * HW_ + c0];
            int i1 = tid + 256,  r1 = i1 >> 5, c1 = (i1 & 31) * 4;
            *(float4*)&Xs[r1][c1] = *(const float4*)&xb[(size_t)(kc + r1) * HW_ + c1];
        }
        __syncthreads();
        float tacc[8][4];
#pragma unroll
        for (int i = 0; i < 8; i++)
#pragma unroll
            for (int j = 0; j < 4; j++) tacc[i][j] = 0.f;
#pragma unroll
        for (int k = 0; k < 16; k++) {
            float4 bx = *(const float4*)&Xs[k][cp];
            float bv[4] = { bx.x, bx.y, bx.z, bx.w };
#pragma unroll
            for (int i = 0; i < 8; i++) {
                float a = Ws[k][ro + i];   // warp-uniform broadcast
#pragma unroll
                for (int j = 0; j < 4; j++) tacc[i][j] += a * bv[j];
            }
        }
#pragma unroll
        for (int i = 0; i < 8; i++)
#pragma unroll
            for (int j = 0; j < 4; j++) acc[i][j] += tacc[i][j];
        __syncthreads();
    }
    float* zrow = g_z + (size_t)b * C_ * HW_ + pb;
#pragma unroll
    for (int i = 0; i < 8; i++) {
        float be = g_beff[ro + i];
        float4 v;
        v.x = acc[i][0] + be; v.y = acc[i][1] + be;
        v.z = acc[i][2] + be; v.w = acc[i][3] + be;
        *(float4*)&zrow[(size_t)(ro + i) * HW_ + cp] = v;
    }
}

// ---------------- K4: codebook norms + hsw --------------------------------
__global__ void k_en(const float* __restrict__ emb, const float* __restrict__ r)
{
    int j = threadIdx.x;                 // 512 threads
    const float* e = emb + j * 64;
    float p0 = 0, p1 = 0, p2 = 0, p3 = 0;
#pragma unroll
    for (int k = 0; k < 64; k += 4) {
        p0 += e[k] * e[k];         p1 += e[k + 1] * e[k + 1];
        p2 += e[k + 2] * e[k + 2]; p3 += e[k + 3] * e[k + 3];
    }
    float s = (p0 + p1) + (p2 + p3);
    float en = sqrtf(s);
    g_e2[j] = s; g_en[j] = en;
    float d = r[j] - en;
    __shared__ float sh[512];
    sh[j] = d * d; __syncthreads();
    for (int o = 256; o > 0; o >>= 1) { if (j < o) sh[j] += sh[j + o]; __syncthreads(); }
    if (j == 0) g_hsw = sh[0] / 512.0f;
}

// ---------------- K5: angular stats (one row/column per block) ------------
__global__ __launch_bounds__(256) void k_cbstats(const float* __restrict__ emb)
{
    int j = blockIdx.x, tid = threadIdx.x;
    __shared__ float ej[64];
    __shared__ float ang[512];
    if (tid < 64) ej[tid] = emb[j * 64 + tid];
    __syncthreads();
    float enj = g_en[j];
    for (int i = tid; i < 512; i += 256) {
        const float* ei = emb + i * 64;
        float p0 = 0, p1 = 0, p2 = 0, p3 = 0;
#pragma unroll
        for (int k = 0; k < 64; k += 4) {
            p0 += ei[k] * ej[k];         p1 += ei[k + 1] * ej[k + 1];
            p2 += ei[k + 2] * ej[k + 2]; p3 += ei[k + 3] * ej[k + 3];
        }
        float d = (p0 + p1) + (p2 + p3);
        float c = d / (g_en[i] * enj);
        c = fminf(fmaxf(c, -0.99999f), 0.99999f);
        ang[i] = acosf(c);
    }
    __syncthreads();
    __shared__ float rs[256];
    float a0 = ang[tid], a1 = ang[tid + 256];
    rs[tid] = a0 + a1; __syncthreads();
    for (int o = 128; o > 0; o >>= 1) { if (tid < o) rs[tid] += rs[tid + o]; __syncthreads(); }
    float mean = rs[0] / 512.0f;
    __syncthreads();
    float d0 = a0 - mean, d1 = a1 - mean;
    rs[tid] = d0 * d0 + d1 * d1; __syncthreads();
    for (int o = 128; o > 0; o >>= 1) { if (tid < o) rs[tid] += rs[tid + o]; __syncthreads(); }
    if (tid == 0) g_var[j] = rs[0] / 511.0f;     // ddof=1
    // two smallest angles of this column (== sort(ang,axis=0)[1])
    __shared__ float m1s[256], m2s[256];
    m1s[tid] = fminf(a0, a1); m2s[tid] = fmaxf(a0, a1);
    __syncthreads();
    for (int o = 128; o > 0; o >>= 1) {
        if (tid < o) {
            float x1 = m1s[tid], x2 = m2s[tid];
            float y1 = m1s[tid + o], y2 = m2s[tid + o];
            float n1 = fminf(x1, y1);
            float n2 = fminf(fmaxf(x1, y1), fminf(x2, y2));
            m1s[tid] = n1; m2s[tid] = n2;
        }
        __syncthreads();
    }
    if (tid == 0) g_cm2[j] = m2s[0];
}

// ---------------- K6: VQ — distance GEMM + top-2 argmin + double re-rank ---
// block: 64 tokens x 512 codes; thread tile 8 tokens x 2 codes per 64-chunk
__global__ __launch_bounds__(256) void k_vq(const float* __restrict__ emb,
                                            float* __restrict__ zq)
{
    __shared__ float Zs[64][65];     // [k][token]  (stride 65 -> conflict-free cols)
    __shared__ float Es[64][66];     // [k][code]   chunk of 64 codes
    __shared__ float zsq_s[64];
    __shared__ float e2s[64];
    __shared__ float warp_mse[8];

    int tid = threadIdx.x;
    int t0  = blockIdx.x * 64;
    const float* zb = g_z + (size_t)t0 * 64;

#pragma unroll
    for (int it = 0; it < 16; it++) {
        int idx = tid + it * 256;              // 4096 elems
        Zs[idx & 63][idx >> 6] = zb[idx];      // coalesced read, transposed store
    }
    __syncthreads();
    if (tid < 64) {
        float p0 = 0, p1 = 0, p2 = 0, p3 = 0;
#pragma unroll
        for (int k = 0; k < 64; k += 4) {
            float a = Zs[k][tid], b = Zs[k + 1][tid], c = Zs[k + 2][tid], d = Zs[k + 3][tid];
            p0 += a * a; p1 += b * b; p2 += c * c; p3 += d * d;
        }
        zsq_s[tid] = (p0 + p1) + (p2 + p3);
    }

    int warp = tid >> 5, lane = tid & 31;
    int ro = warp * 8;          // 8 tokens per warp (warp-uniform)
    int ce = lane * 2;          // 2 codes per lane per chunk
    float v1[8], v2[8]; int i1[8], i2[8];
#pragma unroll
    for (int i = 0; i < 8; i++) { v1[i] = FLT_MAX; v2[i] = FLT_MAX; i1[i] = 0; i2[i] = 0; }

    for (int e0 = 0; e0 < NE_; e0 += 64) {
        __syncthreads();
#pragma unroll
        for (int it = 0; it < 16; it++) {
            int idx = tid + it * 256;
            int e = idx >> 6, k = idx & 63;
            Es[k][e] = emb[(e0 + e) * 64 + k];
        }
        if (tid < 64) e2s[tid] = g_e2[e0 + tid];
        __syncthreads();

        float acc[8][2];
#pragma unroll
        for (int i = 0; i < 8; i++) { acc[i][0] = 0.f; acc[i][1] = 0.f; }
#pragma unroll 4
        for (int k = 0; k < 64; k++) {
            float b0 = Es[k][ce], b1 = Es[k][ce + 1];
#pragma unroll
            for (int i = 0; i < 8; i++) {
                float a = Zs[k][ro + i];       // warp-uniform broadcast
                acc[i][0] += a * b0;
                acc[i][1] += a * b1;
            }
        }
#pragma unroll
        for (int i = 0; i < 8; i++) {
            float zq2 = zsq_s[ro + i];
#pragma unroll
            for (int j = 0; j < 2; j++) {
                float d = (zq2 + e2s[ce + j]) - 2.0f * acc[i][j];  // ref formula/order
                int ei = e0 + ce + j;
                if (d < v1[i])      { v2[i] = v1[i]; i2[i] = i1[i]; v1[i] = d; i1[i] = ei; }
                else if (d < v2[i]) { v2[i] = d; i2[i] = ei; }
            }
        }
    }

    float msum = 0.f;
#pragma unroll
    for (int i = 0; i < 8; i++) {
        float a1 = v1[i], a2 = v2[i]; int ai1 = i1[i], ai2 = i2[i];
        // warp tree-reduce top-2 with argmin-first tie-breaking
#pragma unroll
        for (int off = 16; off > 0; off >>= 1) {
            float b1 = __shfl_down_sync(FULLMASK, a1, off);
            int  bi1 = __shfl_down_sync(FULLMASK, ai1, off);
            float b2 = __shfl_down_sync(FULLMASK, a2, off);
            int  bi2 = __shfl_down_sync(FULLMASK, ai2, off);
            if (b1 < a1 || (b1 == a1 && bi1 < ai1)) {
                float s2; int si2;
                if (a1 < b2 || (a1 == b2 && ai1 < bi2)) { s2 = a1; si2 = ai1; }
                else                                     { s2 = b2; si2 = bi2; }
                a1 = b1; ai1 = bi1; a2 = s2; ai2 = si2;
            } else if (b1 < a2 || (b1 == a2 && bi1 < ai2)) {
                a2 = b1; ai2 = bi1;
            }
        }
        a1  = __shfl_sync(FULLMASK, a1, 0);  ai1 = __shfl_sync(FULLMASK, ai1, 0);
        a2  = __shfl_sync(FULLMASK, a2, 0);  ai2 = __shfl_sync(FULLMASK, ai2, 0);

        int tok = ro + i;
        int chosen = ai1;
        if (a2 - a1 < 2e-3f && ai2 != ai1) {
            // near-tie: exact double-precision re-rank of the two candidates
            const float* ea = emb + (size_t)ai1 * 64;
            const float* eb = emb + (size_t)ai2 * 64;
            double da = 0.0, db = 0.0;
#pragma unroll
            for (int h = 0; h < 2; h++) {
                int k = lane + h * 32;
                double zv = (double)Zs[k][tok];
                double u = zv - (double)ea[k]; da += u * u;
                double w = zv - (double)eb[k]; db += w * w;
            }
#pragma unroll
            for (int off = 16; off > 0; off >>= 1) {
                da += __shfl_down_sync(FULLMASK, da, off);
                db += __shfl_down_sync(FULLMASK, db, off);
            }
            da = __shfl_sync(FULLMASK, da, 0);
            db = __shfl_sync(FULLMASK, db, 0);
            if (db < da || (db == da && ai2 < ai1)) chosen = ai2;
        }

        const float* er = emb + (size_t)chosen * 64;
        float* orow = zq + (size_t)(t0 + tok) * 64;
#pragma unroll
        for (int h = 0; h < 2; h++) {
            int k = lane + h * 32;
            float zv = Zs[k][tok];
            float dv = er[k] - zv;
            orow[k] = zv + dv;              // z + sg(z_q - z), same rounding as ref
            msum += dv * dv;
        }
    }
#pragma unroll
    for (int off = 16; off > 0; off >>= 1)
        msum += __shfl_down_sync(FULLMASK, msum, off);
    if (lane == 0) warp_mse[warp] = msum;
    __syncthreads();
    if (tid == 0) {
        float s = 0.f;
#pragma unroll
        for (int w = 0; w < 8; w++) s += warp_mse[w];
        g_mse_part[blockIdx.x] = s;          // deterministic (no atomics)
    }
}

// ---------------- K7: finalize scalars -------------------------------------
__global__ void k_final(const float* __restrict__ r, float* __restrict__ out)
{
    int t = threadIdx.x;                 // 512 threads
    __shared__ float sh[512];

    sh[t] = g_mse_part[t] + g_mse_part[t + 512]; __syncthreads();
    for (int o = 256; o > 0; o >>= 1) { if (t < o) sh[t] += sh[t + o]; __syncthreads(); }
    float mse_sum = sh[0]; __syncthreads();

    sh[t] = g_var[t]; __syncthreads();
    for (int o = 256; o > 0; o >>= 1) { if (t < o) sh[t] += sh[t + o]; __syncthreads(); }
    float var_sum = sh[0]; __syncthreads();

    sh[t] = g_cm2[t]; __syncthreads();
    for (int o = 256; o > 0; o >>= 1) { if (t < o) sh[t] += sh[t + o]; __syncthreads(); }
    float cm2_sum = sh[0]; __syncthreads();

    sh[t] = fminf(fmaxf(r[t], 0.9f), 1.1f); __syncthreads();
    for (int o = 256; o > 0; o >>= 1) { if (t < o) sh[t] += sh[t + o]; __syncthreads(); }

    if (t == 0) {
        float mse = mse_sum * (1.0f / (float)ZTOT_);
        float cbv = var_sum * (1.0f / 512.0f);
        float tmd = cm2_sum * (1.0f / 512.0f);
        float hsw = g_hsw;
        float loss = ((mse + mse) + hsw) + (cbv - tmd);   // BETA = 1
        out[0] = loss;
        out[1 + ZTOT_ + 0] = cbv;
        out[1 + ZTOT_ + 1] = tmd;
        out[1 + ZTOT_ + 2] = hsw;
        out[1 + ZTOT_ + 3] = 0.0f;                        // cb_loss
        out[1 + ZTOT_ + 4] = sh[0] * (1.0f / 512.0f);     // mean_r
    }
}

// ---------------- launch ----------------------------------------------------
extern "C" void kernel_launch(void* const* d_in, const int* in_sizes, int n_in,
                              void* d_out, int out_size)
{
    (void)in_sizes; (void)n_in; (void)out_size;
    const float* x    = (const float*)d_in[0];
    const float* bng  = (const float*)d_in[1];
    const float* bnb  = (const float*)d_in[2];
    const float* w1   = (const float*)d_in[3];
    const float* b1   = (const float*)d_in[4];
    const float* w2   = (const float*)d_in[5];
    const float* b2   = (const float*)d_in[6];
    const float* emb  = (const float*)d_in[7];
    const float* r    = (const float*)d_in[8];
    float* out = (float*)d_out;

    k_bn     <<<F_,  256>>>(x, bng, bnb);
    k_fuse   <<<C_,  256>>>(w1, b1, w2, b2);
    k_conv   <<<dim3(HW_ / 128, B_), 256>>>(x);
    k_en     <<<1,   512>>>(emb, r);
    k_cbstats<<<NE_, 256>>>(emb);
    k_vq     <<<NBLK_VQ, 256>>>(emb, out + 1);
    k_final  <<<1,   512>>>(r, out);
}

// round 12
// speedup vs baseline: 1.0810x; 1.0767x over previous
#include <cuda_runtime.h>
#include <cfloat>

#define B_    16
#define F_    256
#define C_    64
#define HW_   4096
#define NE_   512
#define ZTOT_ (B_*C_*HW_)    /* 4194304 */
#define NTOK_ (ZTOT_/64)     /* 65536 */
#define NBLK_VQ (NTOK_/64)   /* 1024 */
#define FULLMASK 0xffffffffu

typedef unsigned long long u64;

// ---- packed f32x2 helpers (Blackwell FFMA2 path; ptxas won't emit from C++) ----
__device__ __forceinline__ u64 pack2(float lo, float hi) {
    u64 r; asm("mov.b64 %0,{%1,%2};" : "=l"(r) : "f"(lo), "f"(hi)); return r;
}
__device__ __forceinline__ void unpack2(u64 v, float& lo, float& hi) {
    asm("mov.b64 {%0,%1},%2;" : "=f"(lo), "=f"(hi) : "l"(v));
}
__device__ __forceinline__ void fma2(u64& d, u64 a, u64 b) {
    asm("fma.rn.f32x2 %0,%1,%2,%0;" : "+l"(d) : "l"(a), "l"(b));
}
__device__ __forceinline__ void add2(u64& d, u64 a) {
    asm("add.rn.f32x2 %0,%1,%0;" : "+l"(d) : "l"(a));
}

// ---------------- scratch (device globals; no allocation) ----------------
__device__ __align__(16) float g_z[ZTOT_];        // conv2 output (16 MiB)
__device__ float g_scale[F_], g_shift[F_];        // folded BN affine
__device__ __align__(16) float g_Wt[F_*C_];       // fused weight, [f][o]
__device__ float g_beff[C_];
__device__ float g_en[NE_], g_e2[NE_];
__device__ float g_var[NE_], g_cm2[NE_];
__device__ float g_mse_part[NBLK_VQ];

// ---------------- K1: BN stats (blocks 0..255) + codebook norms (256..257) ---
__global__ __launch_bounds__(256) void k_bn_en(const float* __restrict__ x,
                                               const float* __restrict__ gamma,
                                               const float* __restrict__ beta,
                                               const float* __restrict__ emb)
{
    int tid = threadIdx.x;
    if (blockIdx.x < 256) {
        int f = blockIdx.x;
        float s = 0.f, ss = 0.f;
        const float* xf = x + (size_t)f * HW_;
        for (int b = 0; b < B_; b++) {
            const float* p = xf + (size_t)b * F_ * HW_;
            for (int i = tid; i < HW_; i += 256) { float v = p[i]; s += v; ss += v * v; }
        }
        __shared__ float sh[256], sh2[256];
        sh[tid] = s; sh2[tid] = ss; __syncthreads();
        for (int o = 128; o > 0; o >>= 1) {
            if (tid < o) { sh[tid] += sh[tid + o]; sh2[tid] += sh2[tid + o]; }
            __syncthreads();
        }
        if (tid == 0) {
            const float n = (float)(B_ * HW_);
            float mu  = sh[0] / n;
            float var = sh2[0] / n - mu * mu;
            float sc  = gamma[f] * (1.0f / sqrtf(var + 1e-5f));
            g_scale[f] = sc;
            g_shift[f] = beta[f] - mu * sc;
        }
    } else {
        // codebook norms: one thread per row, identical chains to prior rounds
        int j = (blockIdx.x - 256) * 256 + tid;    // 0..511
        const float* e = emb + (size_t)j * 64;
        float p0 = 0, p1 = 0, p2 = 0, p3 = 0;
#pragma unroll
        for (int k = 0; k < 64; k += 4) {
            p0 += e[k] * e[k];         p1 += e[k + 1] * e[k + 1];
            p2 += e[k + 2] * e[k + 2]; p3 += e[k + 3] * e[k + 3];
        }
        float s = (p0 + p1) + (p2 + p3);
        g_e2[j] = s; g_en[j] = sqrtf(s);
    }
}

// ---------------- K2: weight fusion (blocks 0..63) + angular stats (64..575) --
__global__ __launch_bounds__(256) void k_fuse_cb(const float* __restrict__ w1,
                                                 const float* __restrict__ b1,
                                                 const float* __restrict__ w2,
                                                 const float* __restrict__ b2,
                                                 const float* __restrict__ emb)
{
    int tid = threadIdx.x;
    if (blockIdx.x < 64) {
        int o = blockIdx.x, f = tid;
        float d = 0.f;
#pragma unroll 8
        for (int c = 0; c < C_; c++) d += w2[o * C_ + c] * w1[c * F_ + f];
        g_Wt[f * C_ + o] = d * g_scale[f];
        __shared__ float shf[256];
        shf[f] = d * g_shift[f];
        __syncthreads();
        for (int s = 128; s > 0; s >>= 1) { if (f < s) shf[f] += shf[f + s]; __syncthreads(); }
        if (f == 0) {
            float bv = b2[o];
            for (int c = 0; c < C_; c++) bv += w2[o * C_ + c] * b1[c];
            g_beff[o] = shf[0] + bv;
        }
    } else {
        int j = blockIdx.x - 64;
        __shared__ float ej[64];
        __shared__ float ang[512];
        if (tid < 64) ej[tid] = emb[j * 64 + tid];
        __syncthreads();
        float enj = g_en[j];
        for (int i = tid; i < 512; i += 256) {
            const float* ei = emb + i * 64;
            float p0 = 0, p1 = 0, p2 = 0, p3 = 0;
#pragma unroll
            for (int k = 0; k < 64; k += 4) {
                p0 += ei[k] * ej[k];         p1 += ei[k + 1] * ej[k + 1];
                p2 += ei[k + 2] * ej[k + 2]; p3 += ei[k + 3] * ej[k + 3];
            }
            float d = (p0 + p1) + (p2 + p3);
            float c = d / (g_en[i] * enj);
            c = fminf(fmaxf(c, -0.99999f), 0.99999f);
            ang[i] = acosf(c);
        }
        __syncthreads();
        __shared__ float rs[256];
        float a0 = ang[tid], a1 = ang[tid + 256];
        rs[tid] = a0 + a1; __syncthreads();
        for (int o = 128; o > 0; o >>= 1) { if (tid < o) rs[tid] += rs[tid + o]; __syncthreads(); }
        float mean = rs[0] / 512.0f;
        __syncthreads();
        float d0 = a0 - mean, d1 = a1 - mean;
        rs[tid] = d0 * d0 + d1 * d1; __syncthreads();
        for (int o = 128; o > 0; o >>= 1) { if (tid < o) rs[tid] += rs[tid + o]; __syncthreads(); }
        if (tid == 0) g_var[j] = rs[0] / 511.0f;
        __shared__ float m1s[256], m2s[256];
        m1s[tid] = fminf(a0, a1); m2s[tid] = fmaxf(a0, a1);
        __syncthreads();
        for (int o = 128; o > 0; o >>= 1) {
            if (tid < o) {
                float x1 = m1s[tid], x2 = m2s[tid];
                float y1 = m1s[tid + o], y2 = m2s[tid + o];
                float n1 = fminf(x1, y1);
                float n2 = fminf(fmaxf(x1, y1), fminf(x2, y2));
                m1s[tid] = n1; m2s[tid] = n2;
            }
            __syncthreads();
        }
        if (tid == 0) g_cm2[j] = m2s[0];
    }
}

// ---------------- K3: fused conv GEMM with FFMA2 (pixel pairs) -------------
__global__ __launch_bounds__(256) void k_conv(const float* __restrict__ x)
{
    __shared__ float2 Wsd[16][64];   // duplicated (w,w) -> pack-free FFMA2 operand
    __shared__ float  Xs[16][128];
    int tid = threadIdx.x;
    int b   = blockIdx.y;
    int pb  = blockIdx.x * 128;
    const float* xb = x + (size_t)b * F_ * HW_ + pb;

    int ro = (tid >> 5) * 8;        // 8 output channels per thread (warp-uniform)
    int cp = (tid & 31) * 4;        // 4 pixels per thread (2 f32x2 pairs)

    u64 acc2[8][2];
#pragma unroll
    for (int i = 0; i < 8; i++) { acc2[i][0] = 0ull; acc2[i][1] = 0ull; }

    for (int kc = 0; kc < F_; kc += 16) {
        {
            int r = tid >> 4, c = (tid & 15) * 4;
            float4 w = *(const float4*)&g_Wt[(kc + r) * C_ + c];
            Wsd[r][c    ] = make_float2(w.x, w.x);
            Wsd[r][c + 1] = make_float2(w.y, w.y);
            Wsd[r][c + 2] = make_float2(w.z, w.z);
            Wsd[r][c + 3] = make_float2(w.w, w.w);
            int i0 = tid,        r0 = i0 >> 5, c0 = (i0 & 31) * 4;
            *(float4*)&Xs[r0][c0] = *(const float4*)&xb[(size_t)(kc + r0) * HW_ + c0];
            int i1 = tid + 256,  r1 = i1 >> 5, c1 = (i1 & 31) * 4;
            *(float4*)&Xs[r1][c1] = *(const float4*)&xb[(size_t)(kc + r1) * HW_ + c1];
        }
        __syncthreads();
        u64 t2[8][2];
#pragma unroll
        for (int i = 0; i < 8; i++) { t2[i][0] = 0ull; t2[i][1] = 0ull; }
#pragma unroll
        for (int k = 0; k < 16; k++) {
            u64 x01 = *(const u64*)&Xs[k][cp];
            u64 x23 = *(const u64*)&Xs[k][cp + 2];
#pragma unroll
            for (int i = 0; i < 8; i++) {
                u64 aa = *(const u64*)&Wsd[k][ro + i];   // warp-uniform broadcast
                fma2(t2[i][0], aa, x01);
                fma2(t2[i][1], aa, x23);
            }
        }
#pragma unroll
        for (int i = 0; i < 8; i++) { add2(acc2[i][0], t2[i][0]); add2(acc2[i][1], t2[i][1]); }
        __syncthreads();
    }
    float* zrow = g_z + (size_t)b * C_ * HW_ + pb;
#pragma unroll
    for (int i = 0; i < 8; i++) {
        float be = g_beff[ro + i];
        float a0, a1, a2, a3;
        unpack2(acc2[i][0], a0, a1);
        unpack2(acc2[i][1], a2, a3);
        float4 v;
        v.x = a0 + be; v.y = a1 + be; v.z = a2 + be; v.w = a3 + be;
        *(float4*)&zrow[(size_t)(ro + i) * HW_ + cp] = v;
    }
}

// ---------------- K4: VQ — FFMA2 distance GEMM + top-2 + double re-rank ----
// 64 tokens/block, code chunks of 128 (4 codes/lane, code = lane+32j), token
// pairs packed into f32x2. Dynamic smem layout (floats):
//   Zs[64][66]  @0        (4224)
//   zsq  [64]   @4224
//   e2s  [128]  @4288
//   wmse [8]    @4416
//   Es[64][130] @4424     (8320)  -> total 12744 floats = 50976 B
#define VQ_SMEM_BYTES (12744 * 4)
__global__ __launch_bounds__(256, 2) void k_vq(const float* __restrict__ emb,
                                               float* __restrict__ zq)
{
    extern __shared__ float sm[];
    float* Zs    = sm;
    float* zsq_s = sm + 4224;
    float* e2s   = sm + 4288;
    float* wmse  = sm + 4416;
    float* Es    = sm + 4424;

    int tid = threadIdx.x;
    int t0  = blockIdx.x * 64;
    const float* zb = g_z + (size_t)t0 * 64;

#pragma unroll
    for (int it = 0; it < 16; it++) {
        int idx = tid + it * 256;
        Zs[(idx & 63) * 66 + (idx >> 6)] = zb[idx];   // coalesced read, transposed store
    }
    __syncthreads();
    if (tid < 64) {
        float p0 = 0, p1 = 0, p2 = 0, p3 = 0;
#pragma unroll
        for (int k = 0; k < 64; k += 4) {
            float a = Zs[k * 66 + tid],       b = Zs[(k + 1) * 66 + tid];
            float c = Zs[(k + 2) * 66 + tid], d = Zs[(k + 3) * 66 + tid];
            p0 += a * a; p1 += b * b; p2 += c * c; p3 += d * d;
        }
        zsq_s[tid] = (p0 + p1) + (p2 + p3);
    }

    int warp = tid >> 5, lane = tid & 31;
    int ro = warp * 8;               // 8 tokens = 4 f32x2 pairs (warp-uniform)
    float v1[8], v2[8]; int i1[8], i2[8];
#pragma unroll
    for (int i = 0; i < 8; i++) { v1[i] = FLT_MAX; v2[i] = FLT_MAX; i1[i] = 0; i2[i] = 0; }

#pragma unroll 1
    for (int e0 = 0; e0 < NE_; e0 += 128) {
        __syncthreads();
#pragma unroll
        for (int it = 0; it < 32; it++) {
            int idx = tid + it * 256;             // 8192 elems
            int c = idx >> 6, k = idx & 63;
            Es[k * 130 + c] = emb[(size_t)(e0 + c) * 64 + k];
        }
        if (tid < 128) e2s[tid] = g_e2[e0 + tid];
        __syncthreads();

        u64 acc2[4][4];
#pragma unroll
        for (int p = 0; p < 4; p++)
#pragma unroll
            for (int j = 0; j < 4; j++) acc2[p][j] = 0ull;

#pragma unroll 4
        for (int k = 0; k < 64; k++) {
            const float* zr = Zs + k * 66 + ro;
            u64 z0 = *(const u64*)(zr);
            u64 z1 = *(const u64*)(zr + 2);
            u64 z2 = *(const u64*)(zr + 4);
            u64 z3 = *(const u64*)(zr + 6);
            const float* er = Es + k * 130 + lane;
#pragma unroll
            for (int j = 0; j < 4; j++) {
                float bv = er[32 * j];
                u64 bb = pack2(bv, bv);
                fma2(acc2[0][j], z0, bb);
                fma2(acc2[1][j], z1, bb);
                fma2(acc2[2][j], z2, bb);
                fma2(acc2[3][j], z3, bb);
            }
        }
#pragma unroll
        for (int p = 0; p < 4; p++) {
            float zqa = zsq_s[ro + 2 * p];
            float zqb = zsq_s[ro + 2 * p + 1];
#pragma unroll
            for (int j = 0; j < 4; j++) {        // ascending codes per token
                float d0, d1; unpack2(acc2[p][j], d0, d1);
                float e2v = e2s[lane + 32 * j];
                int ei = e0 + lane + 32 * j;
                int ia = 2 * p, ib = 2 * p + 1;
                float da = (zqa + e2v) - 2.0f * d0;
                if (da < v1[ia])      { v2[ia] = v1[ia]; i2[ia] = i1[ia]; v1[ia] = da; i1[ia] = ei; }
                else if (da < v2[ia]) { v2[ia] = da; i2[ia] = ei; }
                float db = (zqb + e2v) - 2.0f * d1;
                if (db < v1[ib])      { v2[ib] = v1[ib]; i2[ib] = i1[ib]; v1[ib] = db; i1[ib] = ei; }
                else if (db < v2[ib]) { v2[ib] = db; i2[ib] = ei; }
            }
        }
    }

    float msum = 0.f;
#pragma unroll
    for (int i = 0; i < 8; i++) {
        float a1 = v1[i], a2 = v2[i]; int ai1 = i1[i], ai2 = i2[i];
#pragma unroll
        for (int off = 16; off > 0; off >>= 1) {
            float b1 = __shfl_down_sync(FULLMASK, a1, off);
            int  bi1 = __shfl_down_sync(FULLMASK, ai1, off);
            float b2 = __shfl_down_sync(FULLMASK, a2, off);
            int  bi2 = __shfl_down_sync(FULLMASK, ai2, off);
            if (b1 < a1 || (b1 == a1 && bi1 < ai1)) {
                float s2; int si2;
                if (a1 < b2 || (a1 == b2 && ai1 < bi2)) { s2 = a1; si2 = ai1; }
                else                                     { s2 = b2; si2 = bi2; }
                a1 = b1; ai1 = bi1; a2 = s2; ai2 = si2;
            } else if (b1 < a2 || (b1 == a2 && bi1 < ai2)) {
                a2 = b1; ai2 = bi1;
            }
        }
        a1  = __shfl_sync(FULLMASK, a1, 0);  ai1 = __shfl_sync(FULLMASK, ai1, 0);
        a2  = __shfl_sync(FULLMASK, a2, 0);  ai2 = __shfl_sync(FULLMASK, ai2, 0);

        int tok = ro + i;
        int chosen = ai1;
        if (a2 - a1 < 2e-3f && ai2 != ai1) {
            const float* ea = emb + (size_t)ai1 * 64;
            const float* eb = emb + (size_t)ai2 * 64;
            double da = 0.0, db = 0.0;
#pragma unroll
            for (int h = 0; h < 2; h++) {
                int k = lane + h * 32;
                double zv = (double)Zs[k * 66 + tok];
                double u = zv - (double)ea[k]; da += u * u;
                double w = zv - (double)eb[k]; db += w * w;
            }
#pragma unroll
            for (int off = 16; off > 0; off >>= 1) {
                da += __shfl_down_sync(FULLMASK, da, off);
                db += __shfl_down_sync(FULLMASK, db, off);
            }
            da = __shfl_sync(FULLMASK, da, 0);
            db = __shfl_sync(FULLMASK, db, 0);
            if (db < da || (db == da && ai2 < ai1)) chosen = ai2;
        }

        const float* er = emb + (size_t)chosen * 64;
        float* orow = zq + (size_t)(t0 + tok) * 64;
#pragma unroll
        for (int h = 0; h < 2; h++) {
            int k = lane + h * 32;
            float zv = Zs[k * 66 + tok];
            float dv = er[k] - zv;
            orow[k] = zv + dv;
            msum += dv * dv;
        }
    }
#pragma unroll
    for (int off = 16; off > 0; off >>= 1)
        msum += __shfl_down_sync(FULLMASK, msum, off);
    if ((tid & 31) == 0) wmse[warp] = msum;
    __syncthreads();
    if (tid == 0) {
        float s = 0.f;
#pragma unroll
        for (int w = 0; w < 8; w++) s += wmse[w];
        g_mse_part[blockIdx.x] = s;
    }
}

// ---------------- K5: finalize scalars -------------------------------------
__global__ void k_final(const float* __restrict__ r, float* __restrict__ out)
{
    int t = threadIdx.x;                 // 512 threads
    __shared__ float sh[512];

    sh[t] = g_mse_part[t] + g_mse_part[t + 512]; __syncthreads();
    for (int o = 256; o > 0; o >>= 1) { if (t < o) sh[t] += sh[t + o]; __syncthreads(); }
    float mse_sum = sh[0]; __syncthreads();

    sh[t] = g_var[t]; __syncthreads();
    for (int o = 256; o > 0; o >>= 1) { if (t < o) sh[t] += sh[t + o]; __syncthreads(); }
    float var_sum = sh[0]; __syncthreads();

    sh[t] = g_cm2[t]; __syncthreads();
    for (int o = 256; o > 0; o >>= 1) { if (t < o) sh[t] += sh[t + o]; __syncthreads(); }
    float cm2_sum = sh[0]; __syncthreads();

    float dd = r[t] - g_en[t];
    sh[t] = dd * dd; __syncthreads();
    for (int o = 256; o > 0; o >>= 1) { if (t < o) sh[t] += sh[t + o]; __syncthreads(); }
    float hsw = sh[0] / 512.0f; __syncthreads();

    sh[t] = fminf(fmaxf(r[t], 0.9f), 1.1f); __syncthreads();
    for (int o = 256; o > 0; o >>= 1) { if (t < o) sh[t] += sh[t + o]; __syncthreads(); }

    if (t == 0) {
        float mse = mse_sum * (1.0f / (float)ZTOT_);
        float cbv = var_sum * (1.0f / 512.0f);
        float tmd = cm2_sum * (1.0f / 512.0f);
        float loss = ((mse + mse) + hsw) + (cbv - tmd);   // BETA = 1
        out[0] = loss;
        out[1 + ZTOT_ + 0] = cbv;
        out[1 + ZTOT_ + 1] = tmd;
        out[1 + ZTOT_ + 2] = hsw;
        out[1 + ZTOT_ + 3] = 0.0f;                        // cb_loss
        out[1 + ZTOT_ + 4] = sh[0] * (1.0f / 512.0f);     // mean_r
    }
}

// ---------------- launch ----------------------------------------------------
extern "C" void kernel_launch(void* const* d_in, const int* in_sizes, int n_in,
                              void* d_out, int out_size)
{
    (void)in_sizes; (void)n_in; (void)out_size;
    const float* x    = (const float*)d_in[0];
    const float* bng  = (const float*)d_in[1];
    const float* bnb  = (const float*)d_in[2];
    const float* w1   = (const float*)d_in[3];
    const float* b1   = (const float*)d_in[4];
    const float* w2   = (const float*)d_in[5];
    const float* b2   = (const float*)d_in[6];
    const float* emb  = (const float*)d_in[7];
    const float* r    = (const float*)d_in[8];
    float* out = (float*)d_out;

    cudaFuncSetAttribute(k_vq, cudaFuncAttributeMaxDynamicSharedMemorySize, VQ_SMEM_BYTES);

    k_bn_en  <<<258, 256>>>(x, bng, bnb, emb);
    k_fuse_cb<<<576, 256>>>(w1, b1, w2, b2, emb);
    k_conv   <<<dim3(HW_ / 128, B_), 256>>>(x);
    k_vq     <<<NBLK_VQ, 256, VQ_SMEM_BYTES>>>(emb, out + 1);
    k_final  <<<1, 512>>>(r, out);
}